// round 8
// baseline (speedup 1.0000x reference)
#include <cuda_runtime.h>
#include <cstdint>

#define KSEL   100
#define ESTR   128
#define BMAX   256
#define CAP    2048
#define TPB    256
#define SEGCAP 128
#define NSEG   12
#define T0     8.3f   // filter threshold; exact fallback covers any input

// Scratch (__device__ globals; zero-init at load; every counter is reset by
// its consumer each invocation -> graph replays are deterministic).
__device__ int                g_cnt[BMAX];
__device__ int                g_done[BMAX];
__device__ int                g_rows;
__device__ unsigned long long g_buf[BMAX * CAP];
__device__ float              g_exps[BMAX * ESTR];
__device__ int                g_inds[BMAX * KSEL];

// Order-preserving float->uint key: bigger float => bigger key.
__device__ __forceinline__ unsigned fkey(float f) {
    unsigned u = __float_as_uint(f);
    return u ^ (unsigned)(((int)u >> 31) | 0x80000000);
}
__device__ __forceinline__ float fkey_inv(unsigned kk) {
    unsigned u = (kk & 0x80000000u) ? (kk ^ 0x80000000u) : ~kk;
    return __uint_as_float(u);
}

// ---------------------------------------------------------------------------
// ONE kernel: filter -> (last CTA per row) select -> (last row) sample.
// ---------------------------------------------------------------------------
__global__ __launch_bounds__(TPB, 6)
void fused_kernel(const float* __restrict__ logits,
                  const float* __restrict__ sp,
                  float* __restrict__ out, int V, int B, int nseg) {
    const int b    = blockIdx.x;
    const int s    = blockIdx.y;
    const int tid  = threadIdx.x;
    const int lane = tid & 31;
    const int wid  = tid >> 5;

    const float*  row = logits + (size_t)b * V;
    const int     V4  = V >> 2;
    const float4* r4  = (const float4*)row;

    __shared__ unsigned s_n, s_nc;
    __shared__ int s_base, s_flag;
    __shared__ int s_part[TPB / 32];
    __shared__ unsigned long long s_loc[SEGCAP];
    __shared__ unsigned long long s_cand[512];
    __shared__ float s_inv[BMAX];

    if (tid == 0) s_n = 0;
    __syncthreads();

    // ==== Phase F: filter my segment (batch-4 float4 loads for MLP) ====
    const int segLen = (V4 + nseg - 1) / nseg;
    const int q0 = s * segLen;
    const int q1 = min(V4, q0 + segLen);

    for (int i0 = q0; i0 < q1; i0 += TPB * 4) {
        float4 v[4]; int id[4]; bool ok[4];
#pragma unroll
        for (int j = 0; j < 4; j++) {
            id[j] = i0 + j * TPB + tid;
            ok[j] = id[j] < q1;
            if (ok[j]) v[j] = r4[id[j]];
        }
#pragma unroll
        for (int j = 0; j < 4; j++) {
            if (ok[j]) {
                float m = fmaxf(fmaxf(v[j].x, v[j].y), fmaxf(v[j].z, v[j].w));
                if (m > T0) {                       // rare (~1% of quads)
                    const int base = id[j] * 4;
                    float vv[4] = {v[j].x, v[j].y, v[j].z, v[j].w};
#pragma unroll
                    for (int q = 0; q < 4; q++) {
                        if (vv[q] > T0) {
                            unsigned p = atomicAdd(&s_n, 1u);
                            if (p < SEGCAP)
                                s_loc[p] =
                                    ((unsigned long long)fkey(vv[q]) << 32) |
                                    (unsigned)(0xFFFFFFFFu - (unsigned)(base + q));
                        }
                    }
                }
            }
        }
    }
    if (s == 0) {                                    // scalar tail
        for (int i = V4 * 4 + tid; i < V; i += TPB) {
            float x = row[i];
            if (x > T0) {
                unsigned p = atomicAdd(&s_n, 1u);
                if (p < SEGCAP)
                    s_loc[p] = ((unsigned long long)fkey(x) << 32) |
                               (unsigned)(0xFFFFFFFFu - (unsigned)i);
            }
        }
    }
    __syncthreads();

    if (tid == 0) {
        unsigned nsu = s_n;
        int add = (nsu > SEGCAP) ? 1000000 : (int)nsu;   // poison -> fallback
        s_base = atomicAdd(&g_cnt[b], add);
    }
    __syncthreads();
    {
        int ns = min((int)s_n, SEGCAP);
        unsigned long long* buf = g_buf + (size_t)b * CAP;
        for (int t = tid; t < ns; t += TPB) {
            int pos = s_base + t;
            if (pos < CAP) buf[pos] = s_loc[t];
        }
    }
    __threadfence();
    __syncthreads();
    if (tid == 0) {
        int old = atomicAdd(&g_done[b], 1);
        s_flag = (old == nseg - 1);
    }
    __syncthreads();
    if (!s_flag) return;

    // ==== Phase S: last CTA of row b performs selection ====
    __threadfence();
    if (tid == 0) g_done[b] = 0;            // reset for next replay
    const int n = g_cnt[b];

    if (n >= KSEL && n <= 512) {
        const unsigned long long* buf = g_buf + (size_t)b * CAP;
        for (int t = tid; t < 512; t += TPB)
            s_cand[t] = (t < n) ? buf[t] : 0ull;
        __syncthreads();
    } else {
        // exact fallback: bitwise binary search over the full row
        unsigned X = 0;
        for (int bit = 31; bit >= 0; --bit) {
            unsigned trial = X | (1u << bit);
            int local = 0;
            for (int i = tid; i < V; i += TPB)
                local += (fkey(row[i]) >= trial);
#pragma unroll
            for (int off = 16; off; off >>= 1)
                local += __shfl_down_sync(0xffffffffu, local, off);
            if (lane == 0) s_part[wid] = local;
            __syncthreads();
            int cnt = 0;
#pragma unroll
            for (int w = 0; w < TPB / 32; w++) cnt += s_part[w];
            __syncthreads();
            if (cnt >= KSEL) X = trial;
        }
        if (tid == 0) s_nc = 0;
        for (int t = tid; t < 512; t += TPB) s_cand[t] = 0ull;
        __syncthreads();
        for (int i = tid; i < V; i += TPB) {
            unsigned kk = fkey(row[i]);
            if (kk >= X) {
                unsigned p = atomicAdd(&s_nc, 1u);
                if (p < 512)
                    s_cand[p] = ((unsigned long long)kk << 32) |
                                (unsigned)(0xFFFFFFFFu - (unsigned)i);
            }
        }
        __syncthreads();
    }
    if (tid == 0) g_cnt[b] = 0;             // reset for next replay

    // bitonic sort 512 desc with 256 threads (pairs disjoint per step)
    for (int ksz = 2; ksz <= 512; ksz <<= 1) {
        for (int j = ksz >> 1; j > 0; j >>= 1) {
            for (int t = tid; t < 512; t += TPB) {
                int ixj = t ^ j;
                if (ixj > t) {
                    bool desc = ((t & ksz) == 0);
                    unsigned long long a = s_cand[t], bb = s_cand[ixj];
                    if (desc ? (a < bb) : (a > bb)) {
                        s_cand[t] = bb;
                        s_cand[ixj] = a;
                    }
                }
            }
            __syncthreads();
        }
    }

    // emit sorted top-100 indices + exp terms (zero-padded to ESTR)
    if (tid < ESTR) {
        float e = 0.f;
        if (tid < KSEL) {
            unsigned long long comp = s_cand[tid];
            float val = fkey_inv((unsigned)(comp >> 32));
            g_inds[b * KSEL + tid] =
                (int)(0xFFFFFFFFu - (unsigned)(comp & 0xFFFFFFFFu));
            float v0 = fkey_inv((unsigned)(s_cand[0] >> 32));
            int   k  = min(max((int)sp[b * 3 + 0], 1), KSEL);
            float T  = sp[b * 3 + 2];
            if (tid < k) e = expf(val / T - v0 / T);
        }
        g_exps[b * ESTR + tid] = e;
    }
    __threadfence();
    __syncthreads();
    if (tid == 0) {
        int old = atomicAdd(&g_rows, 1);
        s_flag = (old == B - 1);
    }
    __syncthreads();
    if (!s_flag) return;

    // ==== Phase P: final CTA samples all rows (warp per row, stride NW) ====
    if (tid == 0) g_rows = 0;               // reset for next replay
    __threadfence();

    const int NW = TPB / 32;
    for (int r = wid; r < B; r += NW) {
        const float* e = g_exps + r * ESTR;
        float ssum = 0.f;
#pragma unroll
        for (int c = 0; c < 4; c++) ssum += e[c * 32 + lane];
#pragma unroll
        for (int off = 16; off; off >>= 1)
            ssum += __shfl_xor_sync(0xffffffffu, ssum, off);
        if (lane == 0) s_inv[r] = 1.0f / ssum;   // csum[r][0]
    }
    __syncthreads();

    // jnp.min(csum) over the whole matrix = min_b 1/S_b
    float mn = s_inv[0];
    for (int i = 1; i < B; i++) mn = fminf(mn, s_inv[i]);

    for (int r = wid; r < B; r += NW) {
        const float* e = g_exps + r * ESTR;
        int   k    = min(max((int)sp[r * 3 + 0], 1), KSEL);
        float topp = sp[r * 3 + 1];
        float eff  = fmaxf(mn, topp);

        float p[4];
        float carry = 0.f;
#pragma unroll
        for (int c = 0; c < 4; c++) {
            float x = e[c * 32 + lane];
#pragma unroll
            for (int off = 1; off < 32; off <<= 1) {
                float y = __shfl_up_sync(0xffffffffu, x, off);
                if (lane >= off) x += y;
            }
            float pv = x + carry;
            p[c] = pv;
            carry = __shfl_sync(0xffffffffu, pv, 31);
        }
        float S = carry;
        float invS = 1.0f / S;

        // survivors = prefix {i<k : csum_i <= eff}, at least 1
        int ns = 0;
#pragma unroll
        for (int c = 0; c < 4; c++) {
            int gi = c * 32 + lane;
            bool cond = (gi < k) && (p[c] * invS <= eff);
            ns += __popc(__ballot_sync(0xffffffffu, cond));
        }
        if (ns < 1) ns = 1;

        // S2 = prefix sum at index ns-1
        int j = ns - 1, cc = j >> 5, ll = j & 31;
        float t0 = __shfl_sync(0xffffffffu, p[0], ll);
        float t1 = __shfl_sync(0xffffffffu, p[1], ll);
        float t2 = __shfl_sync(0xffffffffu, p[2], ll);
        float t3 = __shfl_sync(0xffffffffu, p[3], ll);
        float S2 = (cc == 0) ? t0 : (cc == 1) ? t1 : (cc == 2) ? t2 : t3;

        // counts = #{i<ns : prefix_i/S2 < 0.5}
        float half = 0.5f * S2;
        int cnt = 0;
#pragma unroll
        for (int c = 0; c < 4; c++) {
            int gi = c * 32 + lane;
            bool cond = (gi < ns) && (p[c] < half);
            cnt += __popc(__ballot_sync(0xffffffffu, cond));
        }
        if (cnt > ns - 1) cnt = ns - 1;
        if (cnt < 0) cnt = 0;

        if (lane == 0) out[r] = (float)g_inds[r * KSEL + cnt];
    }
}

// ---------------------------------------------------------------------------
extern "C" void kernel_launch(void* const* d_in, const int* in_sizes, int n_in,
                              void* d_out, int out_size) {
    int li = 0, si = 1;
    if (n_in >= 2 && in_sizes[0] < in_sizes[1]) { li = 1; si = 0; }
    const float* logits = (const float*)d_in[li];
    const float* sp     = (const float*)d_in[si];
    int B = in_sizes[si] / 3;
    int V = in_sizes[li] / B;
    if (B > BMAX) B = BMAX;

    dim3 grid(B, NSEG);
    fused_kernel<<<grid, TPB>>>(logits, sp, (float*)d_out, V, B, NSEG);
}